// round 17
// baseline (speedup 1.0000x reference)
#include <cuda_runtime.h>
#include <cuda_fp16.h>
#include <stdint.h>

#define B_DIM 128
#define V_DIM 1024
#define I_DIM 512
#define O_DIM 512
#define G_DIM 16

#define BM 128
#define BN 128
#define BK 64
#define NITER (I_DIM / BK)
#define THREADS 128

#define SAPAD 72                    // fp16 row stride: 144B (conflict-free LDSM, 16B aligned)
#define A_TILE_E (128 * SAPAD)      // 9216 halves
#define B_TILE_E (128 * SAPAD)      // 9216 halves
#define STAGE_E (A_TILE_E + B_TILE_E)           // 18432 halves
#define SMEM_BYTES (2 * STAGE_E * 2)            // 2 stages -> 73728 B

// ---------------- static scratch: pre-converted fp16 weights ----------------
__device__ __half wh_buf[G_DIM * O_DIM * I_DIM];   // 8 MB

// ---------------- group-index decode (int32/int64 robust) ----------------
__device__ int g_decoded[V_DIM];

__global__ void decode_gidx_kernel(const int* __restrict__ gidx_i32) {
    __shared__ int is_i32;
    const int v = threadIdx.x;
    if (v == 0) is_i32 = 0;
    __syncthreads();
    {
        const int w = gidx_i32[v];
        if (v & 1) { if (w != 0) atomicOr(&is_i32, 1); }
        else       { if (w < 0 || w >= G_DIM) atomicOr(&is_i32, 1); }
    }
    __syncthreads();
    int g = is_i32 ? gidx_i32[v] : gidx_i32[2 * v];
    if (g < 0) g = 0;
    if (g >= G_DIM) g = G_DIM - 1;
    g_decoded[v] = g;
}

// ---------------- helpers ----------------
__device__ __forceinline__ uint32_t pack_h2(__half a, __half b) {
    return (uint32_t)__half_as_ushort(a) | ((uint32_t)__half_as_ushort(b) << 16);
}

// single fp16 conversion of float4
__device__ __forceinline__ uint2 cvt_f16(float4 v) {
    uint2 r;
    r.x = pack_h2(__float2half_rn(v.x), __float2half_rn(v.y));
    r.y = pack_h2(__float2half_rn(v.z), __float2half_rn(v.w));
    return r;
}

__device__ __forceinline__ void mma_f16(float* d, const uint32_t* a, const uint32_t* b) {
    asm volatile(
        "mma.sync.aligned.m16n8k16.row.col.f32.f16.f16.f32 "
        "{%0,%1,%2,%3}, {%4,%5,%6,%7}, {%8,%9}, {%0,%1,%2,%3};"
        : "+f"(d[0]), "+f"(d[1]), "+f"(d[2]), "+f"(d[3])
        : "r"(a[0]), "r"(a[1]), "r"(a[2]), "r"(a[3]), "r"(b[0]), "r"(b[1]));
}

__device__ __forceinline__ void ldsm_x4(uint32_t& r0, uint32_t& r1, uint32_t& r2,
                                        uint32_t& r3, uint32_t addr) {
    asm volatile("ldmatrix.sync.aligned.m8n8.x4.shared.b16 {%0,%1,%2,%3}, [%4];"
                 : "=r"(r0), "=r"(r1), "=r"(r2), "=r"(r3) : "r"(addr));
}

__device__ __forceinline__ void cp_async16(uint32_t smem_addr, const void* gptr) {
    asm volatile("cp.async.cg.shared.global [%0], [%1], 16;"
                 :: "r"(smem_addr), "l"(gptr) : "memory");
}
__device__ __forceinline__ void cp_commit() {
    asm volatile("cp.async.commit_group;" ::: "memory");
}
__device__ __forceinline__ void cp_wait0() {
    asm volatile("cp.async.wait_group 0;" ::: "memory");
}

// ---------------- weight fp16-convert prepass (idempotent) ------
__global__ void convert_w_kernel(const float* __restrict__ w) {
    const int i = blockIdx.x * 256 + threadIdx.x;   // indexes float4 (1M total)
    float4 v = ((const float4*)w)[i];
    ((uint2*)wh_buf)[i] = cvt_f16(v);
}

// ---------------- main kernel ----------------
__global__ void __launch_bounds__(THREADS, 2) glinear_mma_kernel(
    const float* __restrict__ x,        // [B, V, I]
    const float* __restrict__ bias,     // [G, O]
    float* __restrict__ out)            // [B, V, O]
{
    extern __shared__ __half sm[];

    const int tid = threadIdx.x;
    const int wid = tid >> 5;     // 0..3
    const int lid = tid & 31;
    const int q   = lid & 3;      // 0..3
    const int gq  = lid >> 2;     // 0..7
    const int wm  = wid >> 1;     // 0..1  (M tiles of 64)
    const int wn  = wid & 1;      // 0..1  (N tiles of 64)

    const int bid = blockIdx.x;
    const int v   = bid >> 2;
    const int nt  = bid & 3;      // N block of 128
    const int grp = g_decoded[v];

    const float* Ap = x + (size_t)v * I_DIM;
    const __half* Wp = wh_buf + ((size_t)grp * O_DIM + (size_t)nt * BN) * I_DIM;
    const size_t strideA = (size_t)V_DIM * I_DIM;
    const size_t strideC = (size_t)V_DIM * O_DIM;

    const uint32_t smBase = (uint32_t)__cvta_generic_to_shared(sm);
    const uint32_t B_OFF  = A_TILE_E * 2;

    // loader coords (8 chunks per thread, cid = tid + j*128, 0..1023)
    //   r = cid>>3 (0..127), kc = cid&7 (0..7): 8-half (16 B) chunks
    // ldmatrix per-lane base addresses (byte offsets within a stage)
    const int aRow = wm * 64 + (lid & 7) + ((lid >> 3) & 1) * 8;
    const int aK   = (lid >> 4) * 8;
    const uint32_t aOff = (uint32_t)((aRow * SAPAD + aK) * 2);
    const int bRow = wn * 64 + (lid & 7) + (lid >> 4) * 8;
    const int bK   = ((lid >> 3) & 1) * 8;
    const uint32_t bOff = (uint32_t)((bRow * SAPAD + bK) * 2);

    float acc[4][8][4];
#pragma unroll
    for (int a = 0; a < 4; a++)
#pragma unroll
        for (int b = 0; b < 8; b++)
#pragma unroll
            for (int c = 0; c < 4; c++) acc[a][b][c] = 0.0f;

    // ---- fill stage 0 ----
    {
#pragma unroll
        for (int j = 0; j < 8; j++) {
            const int cid = tid + j * THREADS;    // 0..1023
            const int r   = cid >> 3;             // 0..127
            const int kc  = cid & 7;              // 0..7
            const uint32_t dst = smBase + B_OFF + (uint32_t)((r * SAPAD + kc * 8) * 2);
            cp_async16(dst, Wp + (size_t)r * I_DIM + kc * 8);
        }
        cp_commit();
#pragma unroll
        for (int j = 0; j < 8; j++) {
            const int cid = tid + j * THREADS;
            const int r   = cid >> 3;             // 0..127
            const int kc  = (cid & 7) * 8;        // 0..56
            float4 va0 = *(const float4*)(Ap + (size_t)r * strideA + kc);
            float4 va1 = *(const float4*)(Ap + (size_t)r * strideA + kc + 4);
            uint2 c0 = cvt_f16(va0);
            uint2 c1 = cvt_f16(va1);
            *(uint4*)(sm + r * SAPAD + kc) = make_uint4(c0.x, c0.y, c1.x, c1.y);
        }
        cp_wait0();
    }
    __syncthreads();

    uint4 pa[8];   // prefetched A, already converted to fp16

    for (int it = 0; it < NITER; it++) {
        // issue next-stage B cp.async + prefetch-and-convert next A into registers
        if (it + 1 < NITER) {
            const int k0n = (it + 1) * BK;
            const uint32_t nstage = smBase + (uint32_t)((it + 1) & 1) * (STAGE_E * 2);
#pragma unroll
            for (int j = 0; j < 8; j++) {
                const int cid = tid + j * THREADS;
                const int r   = cid >> 3;
                const int kc  = cid & 7;
                const uint32_t dst = nstage + B_OFF + (uint32_t)((r * SAPAD + kc * 8) * 2);
                cp_async16(dst, Wp + (size_t)r * I_DIM + k0n + kc * 8);
            }
            cp_commit();
#pragma unroll
            for (int j = 0; j < 8; j++) {
                const int cid = tid + j * THREADS;
                const int r   = cid >> 3;
                const int kc  = (cid & 7) * 8;
                float4 va0 = *(const float4*)(Ap + (size_t)r * strideA + k0n + kc);
                float4 va1 = *(const float4*)(Ap + (size_t)r * strideA + k0n + kc + 4);
                uint2 c0 = cvt_f16(va0);
                uint2 c1 = cvt_f16(va1);
                pa[j] = make_uint4(c0.x, c0.y, c1.x, c1.y);
            }
        }

        // compute current stage via ldmatrix + single-pass fp16 mma (4 k16 steps)
        {
            const uint32_t stage = smBase + (uint32_t)(it & 1) * (STAGE_E * 2);
            const uint32_t aAddr = stage + aOff;
            const uint32_t bAddr = stage + B_OFF + bOff;

#pragma unroll
            for (int ks = 0; ks < 4; ks++) {
                const uint32_t kd = (uint32_t)(ks * 32);   // 16 halves = 32 B
                uint32_t aF[4][4], bF[8][2];
#pragma unroll
                for (int mf = 0; mf < 4; mf++) {
                    const uint32_t md = (uint32_t)(mf * 16 * SAPAD * 2);
                    ldsm_x4(aF[mf][0], aF[mf][1], aF[mf][2], aF[mf][3],
                            aAddr + md + kd);
                }
#pragma unroll
                for (int nfp = 0; nfp < 4; nfp++) {
                    const uint32_t nd = (uint32_t)(nfp * 16 * SAPAD * 2);
                    ldsm_x4(bF[nfp * 2][0], bF[nfp * 2][1], bF[nfp * 2 + 1][0],
                            bF[nfp * 2 + 1][1], bAddr + nd + kd);
                }
#pragma unroll
                for (int mf = 0; mf < 4; mf++)
#pragma unroll
                    for (int nf = 0; nf < 8; nf++)
                        mma_f16(acc[mf][nf], aF[mf], bF[nf]);
            }
        }

        // store next-stage A, then wait for B cp.async and sync
        if (it + 1 < NITER) {
            __half* nsm = sm + (size_t)((it + 1) & 1) * STAGE_E;
#pragma unroll
            for (int j = 0; j < 8; j++) {
                const int cid = tid + j * THREADS;
                const int r   = cid >> 3;
                const int kc  = (cid & 7) * 8;
                *(uint4*)(nsm + r * SAPAD + kc) = pa[j];
            }
            cp_wait0();
        }
        __syncthreads();
    }

    // ---------------- epilogue: bias + direct stores ----------------
    const float* bptr = bias + (size_t)grp * O_DIM + (size_t)nt * BN;
#pragma unroll
    for (int nf = 0; nf < 8; nf++) {
        const int col = wn * 64 + nf * 8 + 2 * q;
        const float b0 = bptr[col];
        const float b1 = bptr[col + 1];
#pragma unroll
        for (int mf = 0; mf < 4; mf++) {
            const int row0 = wm * 64 + mf * 16 + gq;
            float2 v0, v1;
            v0.x = acc[mf][nf][0] + b0;
            v0.y = acc[mf][nf][1] + b1;
            v1.x = acc[mf][nf][2] + b0;
            v1.y = acc[mf][nf][3] + b1;
            float* o0 = out + (size_t)row0 * strideC + (size_t)v * O_DIM + nt * BN + col;
            *(float2*)o0 = v0;
            *(float2*)(o0 + 8 * strideC) = v1;
        }
    }
}

extern "C" void kernel_launch(void* const* d_in, const int* in_sizes, int n_in,
                              void* d_out, int out_size) {
    const float* x    = nullptr;
    const void*  gidx = nullptr;
    const float* w    = nullptr;
    const float* b    = nullptr;
    for (int i = 0; i < n_in; i++) {
        switch (in_sizes[i]) {
            case 67108864: x    = (const float*)d_in[i]; break;
            case 1024:     gidx = d_in[i];               break;
            case 4194304:  w    = (const float*)d_in[i]; break;
            case 8192:     b    = (const float*)d_in[i]; break;
            default: break;
        }
    }
    if (!x)    x    = (const float*)d_in[0];
    if (!gidx) gidx = d_in[1];
    if (!w)    w    = (const float*)d_in[2];
    if (!b)    b    = (const float*)d_in[3];

    float* out = (float*)d_out;

    static bool attr_done = false;
    if (!attr_done) {
        cudaFuncSetAttribute(glinear_mma_kernel,
                             cudaFuncAttributeMaxDynamicSharedMemorySize, SMEM_BYTES);
        attr_done = true;
    }

    decode_gidx_kernel<<<1, V_DIM>>>((const int*)gidx);
    convert_w_kernel<<<(G_DIM * O_DIM * I_DIM / 4) / 256, 256>>>(w);
    glinear_mma_kernel<<<V_DIM * 4, THREADS, SMEM_BYTES>>>(x, b, out);
}